// round 1
// baseline (speedup 1.0000x reference)
#include <cuda_runtime.h>

#define THREADS 256
#define BLOCKS  1184          // 8 blocks/SM on 148 SMs
#define NSEL    107
#define NLM     543
#define FFRAMES 30

// lips(40) | left_hand(21) | upper_body(25) | right_hand(21)
__device__ __constant__ int d_sel[NSEL] = {
    61,185,40,39,37,0,267,269,270,409,291,
    146,91,181,84,17,314,405,321,375,
    78,191,80,81,82,13,312,311,310,415,
    95,88,178,87,14,317,402,318,324,308,
    468,469,470,471,472,473,474,475,476,477,478,479,480,481,482,483,484,485,486,487,488,
    489,490,491,492,493,494,495,496,497,498,499,500,501,502,503,504,505,506,507,508,509,510,511,512,513,
    522,523,524,525,526,527,528,529,530,531,532,533,534,535,536,537,538,539,540,541,542
};

__device__ float        g_psum [BLOCKS];
__device__ float        g_psum2[BLOCKS];
__device__ int          g_pcnt [BLOCKS];
__device__ unsigned int g_done = 0;
__device__ float        g_stats[2];   // mean, 1/std

__device__ __forceinline__ bool is_nan_bits(float v) {
    return (__float_as_uint(v) & 0x7fffffffu) > 0x7f800000u;
}

__global__ void __launch_bounds__(THREADS)
reduce_kernel(const float* __restrict__ x, long long n) {
    const long long n4 = n >> 2;
    const float4* __restrict__ x4 = reinterpret_cast<const float4*>(x);

    float s0 = 0.f, s1 = 0.f, s2 = 0.f, s3 = 0.f;
    float q0 = 0.f, q1 = 0.f, q2 = 0.f, q3 = 0.f;
    int cnt = 0;

    const long long stride = (long long)gridDim.x * blockDim.x;
    for (long long i = (long long)blockIdx.x * blockDim.x + threadIdx.x; i < n4; i += stride) {
        float4 v = x4[i];
        if (!is_nan_bits(v.x)) { s0 += v.x; q0 = fmaf(v.x, v.x, q0); cnt++; }
        if (!is_nan_bits(v.y)) { s1 += v.y; q1 = fmaf(v.y, v.y, q1); cnt++; }
        if (!is_nan_bits(v.z)) { s2 += v.z; q2 = fmaf(v.z, v.z, q2); cnt++; }
        if (!is_nan_bits(v.w)) { s3 += v.w; q3 = fmaf(v.w, v.w, q3); cnt++; }
    }
    // scalar tail (n not multiple of 4) — block 0 only
    if (blockIdx.x == 0) {
        for (long long i = n4 * 4 + threadIdx.x; i < n; i += blockDim.x) {
            float v = x[i];
            if (!is_nan_bits(v)) { s0 += v; q0 = fmaf(v, v, q0); cnt++; }
        }
    }

    float s = (s0 + s1) + (s2 + s3);
    float q = (q0 + q1) + (q2 + q3);

    __shared__ float sh_s[THREADS];
    __shared__ float sh_q[THREADS];
    __shared__ int   sh_c[THREADS];
    const int tid = threadIdx.x;
    sh_s[tid] = s; sh_q[tid] = q; sh_c[tid] = cnt;
    __syncthreads();
    for (int off = THREADS / 2; off > 0; off >>= 1) {
        if (tid < off) {
            sh_s[tid] += sh_s[tid + off];
            sh_q[tid] += sh_q[tid + off];
            sh_c[tid] += sh_c[tid + off];
        }
        __syncthreads();
    }

    __shared__ bool is_last;
    if (tid == 0) {
        g_psum [blockIdx.x] = sh_s[0];
        g_psum2[blockIdx.x] = sh_q[0];
        g_pcnt [blockIdx.x] = sh_c[0];
        __threadfence();
        unsigned int old = atomicAdd(&g_done, 1u);
        is_last = (old == gridDim.x - 1);
    }
    __syncthreads();
    if (!is_last) return;
    __threadfence();

    // Final reduce of block partials in fp64 (tiny op count; fp32 main loop
    // avoids the B300 fp64 throughput trap).
    __shared__ double    dh_s[THREADS];
    __shared__ double    dh_q[THREADS];
    __shared__ long long dh_c[THREADS];
    double ds = 0.0, dq = 0.0; long long dc = 0;
    for (int i = tid; i < (int)gridDim.x; i += THREADS) {
        ds += (double)g_psum[i];
        dq += (double)g_psum2[i];
        dc += g_pcnt[i];
    }
    dh_s[tid] = ds; dh_q[tid] = dq; dh_c[tid] = dc;
    __syncthreads();
    for (int off = THREADS / 2; off > 0; off >>= 1) {
        if (tid < off) {
            dh_s[tid] += dh_s[tid + off];
            dh_q[tid] += dh_q[tid + off];
            dh_c[tid] += dh_c[tid + off];
        }
        __syncthreads();
    }
    if (tid == 0) {
        double S = dh_s[0], Q = dh_q[0];
        double C = (double)dh_c[0];
        double mean = S / C;
        double var  = (Q - S * S / C) / (C - 1.0);
        g_stats[0] = (float)mean;
        g_stats[1] = (float)(1.0 / sqrt(var));
        g_done = 0;   // reset for next graph replay
    }
}

__global__ void out_kernel(const float* __restrict__ x, float* __restrict__ out, int T) {
    const int total = FFRAMES * NSEL * 3;
    int i = blockIdx.x * blockDim.x + threadIdx.x;
    if (i >= total) return;

    int c = i % 3;
    int l = (i / 3) % NSEL;
    int f = i / (3 * NSEL);

    const float mean = g_stats[0];
    const float istd = g_stats[1];
    const int   lm   = d_sel[l];

    if (T >= FFRAMES) {
        // nearest-exact
        int sf = (int)floor(((double)f + 0.5) * (double)T / (double)FFRAMES);
        if (sf > T - 1) sf = T - 1;
        if (sf < 0)     sf = 0;
        float v = x[(long long)sf * (NLM * 3) + lm * 3 + c];
        out[i] = is_nan_bits(v) ? 0.0f : (v - mean) * istd;
    } else {
        // linear, align_corners=False
        double pos = ((double)f + 0.5) * ((double)T / (double)FFRAMES) - 0.5;
        if (pos < 0.0)            pos = 0.0;
        if (pos > (double)(T - 1)) pos = (double)(T - 1);
        int i0 = (int)floor(pos);
        int i1 = i0 + 1; if (i1 > T - 1) i1 = T - 1;
        float w  = (float)(pos - (double)i0);
        float v0 = x[(long long)i0 * (NLM * 3) + lm * 3 + c];
        float v1 = x[(long long)i1 * (NLM * 3) + lm * 3 + c];
        float y0 = is_nan_bits(v0) ? 0.0f : (v0 - mean) * istd;
        float y1 = is_nan_bits(v1) ? 0.0f : (v1 - mean) * istd;
        out[i] = (1.0f - w) * y0 + w * y1;
    }
}

extern "C" void kernel_launch(void* const* d_in, const int* in_sizes, int n_in,
                              void* d_out, int out_size) {
    const float* x = (const float*)d_in[0];
    long long n = (long long)in_sizes[0];
    int T = (int)(n / (NLM * 3));

    reduce_kernel<<<BLOCKS, THREADS>>>(x, n);

    const int total = FFRAMES * NSEL * 3;
    out_kernel<<<(total + 127) / 128, 128>>>(x, (float*)d_out, T);
}